// round 7
// baseline (speedup 1.0000x reference)
#include <cuda_runtime.h>
#include <math.h>

#define N_PART   16384
#define DDIM     16
#define PDIM     8
#define M_STEPS  50
#define HDIM     128
#define IN_DIM   25        // 1 + D + P
#define BLK_P    128       // particles per CTA
#define NTHREADS 256
#define LDIN     25        // sIn row stride (odd -> conflict-free column access)
#define LDH      132       // sH row stride (mult of 4 for vector ld/st)

typedef unsigned long long u64;

static __device__ __forceinline__ u64 pack2(float x, float y) {
    u64 r;
    asm("mov.b64 %0, {%1, %2};" : "=l"(r) : "f"(x), "f"(y));
    return r;
}
static __device__ __forceinline__ u64 fma2(u64 a, u64 b, u64 c) {
    u64 d;
    asm("fma.rn.f32x2 %0, %1, %2, %3;" : "=l"(d) : "l"(a), "l"(b), "l"(c));
    return d;
}
static __device__ __forceinline__ float2 unpack2(u64 v) {
    float2 f;
    asm("mov.b64 {%0, %1}, %2;" : "=f"(f.x), "=f"(f.y) : "l"(v));
    return f;
}

// C[8x8] tile (as 8x4 f32x2) += A[row0..row0+8, 0..K) * B[0..K, col0..col0+8)
// A: row stride LDA (floats).  B: row stride LDB (floats), col0 8-float (32B) aligned.
template <int K, int LDA, int LDB>
static __device__ __forceinline__ void mm_tile(const float* __restrict__ A,
                                               const float* __restrict__ B,
                                               int row0, int col0,
                                               u64 c[8][4]) {
#pragma unroll 4
    for (int k = 0; k < K; k++) {
        const u64* br = (const u64*)(B + k * LDB + col0);
        u64 b0 = br[0], b1 = br[1], b2 = br[2], b3 = br[3];
        const float* ac = A + row0 * LDA + k;
#pragma unroll
        for (int i = 0; i < 8; i++) {
            float av = ac[i * LDA];
            u64 a2 = pack2(av, av);
            c[i][0] = fma2(a2, b0, c[i][0]);
            c[i][1] = fma2(a2, b1, c[i][1]);
            c[i][2] = fma2(a2, b2, c[i][2]);
            c[i][3] = fma2(a2, b3, c[i][3]);
        }
    }
}

static __device__ __forceinline__ void store_relu_bias(float* __restrict__ dst,
                                                       int row0, int col0,
                                                       const u64 c[8][4],
                                                       const float* __restrict__ bias) {
#pragma unroll
    for (int i = 0; i < 8; i++) {
        float2* drow = (float2*)(dst + (row0 + i) * LDH + col0);
#pragma unroll
        for (int j = 0; j < 4; j++) {
            float2 v = unpack2(c[i][j]);
            v.x = fmaxf(v.x + bias[col0 + 2 * j + 0], 0.0f);
            v.y = fmaxf(v.y + bias[col0 + 2 * j + 1], 0.0f);
            drow[j] = v;
        }
    }
}

__global__ void __launch_bounds__(NTHREADS, 1)
sde_rollout_kernel(const float* __restrict__ X0, const float* __restrict__ V0,
                   const float* __restrict__ obs, const float* __restrict__ noise,
                   const float* __restrict__ W1, const float* __restrict__ b1,
                   const float* __restrict__ W2, const float* __restrict__ b2,
                   const float* __restrict__ W3, const float* __restrict__ b3,
                   float* __restrict__ out) {
    extern __shared__ float sm[];
    float* W1s = sm;                        // 25*128 = 3200
    float* b1s = W1s + IN_DIM * HDIM;       // 128
    float* W2s = b1s + HDIM;                // 128*128 = 16384
    float* b2s = W2s + HDIM * HDIM;         // 128
    float* W3s = b2s + HDIM;                // 128*16 = 2048
    float* b3s = W3s + HDIM * DDIM;         // 16
    float* sIn = b3s + 16;                  // 128*25 = 3200   (offset 21904, 16B aligned)
    float* sH  = sIn + BLK_P * LDIN;        // 128*132 = 16896
    float* sV  = sH + BLK_P * LDH;          // 128

    const int tid = threadIdx.x;
    const int pbase = blockIdx.x * BLK_P;

    // ---- cooperative weight load ----
    for (int i = tid; i < (IN_DIM * HDIM) / 4; i += NTHREADS)
        ((float4*)W1s)[i] = ((const float4*)W1)[i];
    for (int i = tid; i < (HDIM * HDIM) / 4; i += NTHREADS)
        ((float4*)W2s)[i] = ((const float4*)W2)[i];
    for (int i = tid; i < (HDIM * DDIM) / 4; i += NTHREADS)
        ((float4*)W3s)[i] = ((const float4*)W3)[i];
    if (tid < HDIM) { b1s[tid] = b1[tid]; b2s[tid] = b2[tid]; }
    if (tid < DDIM) b3s[tid] = b3[tid];

    // ---- init particle state: sIn row = [t, X(16), obs(8)], sV ----
    const int p  = tid >> 1;
    const int dh = (tid & 1) * 8;
    const int pg = pbase + p;
    {
        float4 xa = *(const float4*)(X0 + (size_t)pg * DDIM + dh);
        float4 xb = *(const float4*)(X0 + (size_t)pg * DDIM + dh + 4);
        float* row = sIn + p * LDIN;
        row[1 + dh + 0] = xa.x; row[1 + dh + 1] = xa.y;
        row[1 + dh + 2] = xa.z; row[1 + dh + 3] = xa.w;
        row[1 + dh + 4] = xb.x; row[1 + dh + 5] = xb.y;
        row[1 + dh + 6] = xb.z; row[1 + dh + 7] = xb.w;
        if ((tid & 1) == 0) {
            row[0] = 0.0f;                 // t = times[0] = 0
            sV[p] = V0[pg];
#pragma unroll
            for (int j = 0; j < PDIM; j++)
                row[1 + DDIM + j] = obs[(size_t)pg * PDIM + j];
        }
    }
    __syncthreads();

    const float dt   = (float)(1.0 / (double)M_STEPS);  // T = 1
    const float sqdt = sqrtf(dt);
    const int ty = tid >> 4, tx = tid & 15;
    const int row0 = ty * 8, col0 = tx * 8;

    for (int m = 0; m < M_STEPS; m++) {
        // ---- layer 1: h1 = relu(In @ W1 + b1) ----
        u64 c[8][4];
#pragma unroll
        for (int i = 0; i < 8; i++) { c[i][0]=0; c[i][1]=0; c[i][2]=0; c[i][3]=0; }
        mm_tile<IN_DIM, LDIN, HDIM>(sIn, W1s, row0, col0, c);
        store_relu_bias(sH, row0, col0, c, b1s);   // sH free (prev step fenced)
        __syncthreads();

        // ---- layer 2: h2 = relu(h1 @ W2 + b2) ----
#pragma unroll
        for (int i = 0; i < 8; i++) { c[i][0]=0; c[i][1]=0; c[i][2]=0; c[i][3]=0; }
        mm_tile<HDIM, LDH, HDIM>(sH, W2s, row0, col0, c);
        __syncthreads();                            // everyone done reading h1
        store_relu_bias(sH, row0, col0, c, b2s);
        __syncthreads();

        // ---- layer 3: Z = h2 @ W3 + b3 ; V,X update (2 threads per particle) ----
        u64 cz[4] = {0, 0, 0, 0};
        const float* hrow = sH + p * LDH;
#pragma unroll 8
        for (int k = 0; k < HDIM; k++) {
            float hv = hrow[k];
            u64 a2 = pack2(hv, hv);
            const u64* wr = (const u64*)(W3s + k * DDIM + dh);
            cz[0] = fma2(a2, wr[0], cz[0]);
            cz[1] = fma2(a2, wr[1], cz[1]);
            cz[2] = fma2(a2, wr[2], cz[2]);
            cz[3] = fma2(a2, wr[3], cz[3]);
        }
        float z[8];
#pragma unroll
        for (int j4 = 0; j4 < 4; j4++) {
            float2 v = unpack2(cz[j4]);
            z[2 * j4 + 0] = v.x + b3s[dh + 2 * j4 + 0];
            z[2 * j4 + 1] = v.y + b3s[dh + 2 * j4 + 1];
        }
        // Brownian increment for my 8 dims
        const float* np = noise + (((size_t)m * N_PART + pg) * DDIM + dh);
        float4 e0 = *(const float4*)np;
        float4 e1 = *(const float4*)(np + 4);
        float eps[8] = {e0.x, e0.y, e0.z, e0.w, e1.x, e1.y, e1.z, e1.w};

        float zz = 0.0f, zw = 0.0f;
#pragma unroll
        for (int j = 0; j < 8; j++) {
            zz = fmaf(z[j], z[j], zz);
            zw = fmaf(z[j], sqdt * eps[j], zw);
        }
        zz += __shfl_xor_sync(0xffffffffu, zz, 1);
        zw += __shfl_xor_sync(0xffffffffu, zw, 1);

        // X <- X*(1-dt) + sqrt(dt)*eps   (sigma = 1)
        float* xr = sIn + p * LDIN + 1 + dh;
#pragma unroll
        for (int j = 0; j < 8; j++)
            xr[j] = fmaf(xr[j], 1.0f - dt, sqdt * eps[j]);

        if ((tid & 1) == 0) {
            sV[p] = sV[p] + dt * 0.5f * zz + zw;     // V update
            sIn[p * LDIN] = (float)(m + 1) * dt;     // t for next step
        }
        __syncthreads();
    }

    // ---- write outputs: X (N*16) then V (N) ----
    {
        float* xo = out + (size_t)pg * DDIM + dh;
        const float* xr = sIn + p * LDIN + 1 + dh;
#pragma unroll
        for (int j = 0; j < 8; j++) xo[j] = xr[j];
        if ((tid & 1) == 0) out[(size_t)N_PART * DDIM + pg] = sV[p];
    }
}

extern "C" void kernel_launch(void* const* d_in, const int* in_sizes, int n_in,
                              void* d_out, int out_size) {
    const float* X0    = (const float*)d_in[0];
    const float* V0    = (const float*)d_in[1];
    const float* obs   = (const float*)d_in[2];
    const float* noise = (const float*)d_in[3];
    const float* W1    = (const float*)d_in[4];
    const float* b1    = (const float*)d_in[5];
    const float* W2    = (const float*)d_in[6];
    const float* b2    = (const float*)d_in[7];
    const float* W3    = (const float*)d_in[8];
    const float* b3    = (const float*)d_in[9];
    float* out = (float*)d_out;

    const size_t smem_bytes =
        (size_t)(IN_DIM * HDIM + HDIM + HDIM * HDIM + HDIM + HDIM * DDIM + 16 +
                 BLK_P * LDIN + BLK_P * LDH + BLK_P) * sizeof(float);

    cudaFuncSetAttribute(sde_rollout_kernel,
                         cudaFuncAttributeMaxDynamicSharedMemorySize,
                         (int)smem_bytes);

    sde_rollout_kernel<<<N_PART / BLK_P, NTHREADS, smem_bytes>>>(
        X0, V0, obs, noise, W1, b1, W2, b2, W3, b3, out);
}

// round 8
// speedup vs baseline: 1.0609x; 1.0609x over previous
#include <cuda_runtime.h>
#include <math.h>

#define N_PART   16384
#define DDIM     16
#define PDIM     8
#define M_STEPS  50
#define HDIM     128
#define KIN      28        // padded 1 + D + P (25) -> 28 for float4 k-vectorization
#define BLK_P    128       // particles per CTA
#define NTHREADS 256
#define LDIN     28        // sIn row stride (mult of 4, 16B-aligned rows)
#define LDH      132       // sH row stride (mult of 4)

typedef unsigned long long u64;

static __device__ __forceinline__ u64 pack2(float x, float y) {
    u64 r;
    asm("mov.b64 %0, {%1, %2};" : "=l"(r) : "f"(x), "f"(y));
    return r;
}
static __device__ __forceinline__ u64 fma2(u64 a, u64 b, u64 c) {
    u64 d;
    asm("fma.rn.f32x2 %0, %1, %2, %3;" : "=l"(d) : "l"(a), "l"(b), "l"(c));
    return d;
}
static __device__ __forceinline__ float2 unpack2(u64 v) {
    float2 f;
    asm("mov.b64 {%0, %1}, %2;" : "=f"(f.x), "=f"(f.y) : "l"(v));
    return f;
}

// C[8x8] tile (8x4 f32x2) += A[row0..+8, 0..4*K4) * B[0..4*K4, col0..+8)
// A rows 16B-aligned, read as float4 chunks of 4 k's (double-buffered).
// B rows read as 4x u64 per k, prefetched one k ahead (guard-free: reads one
// row past B and one chunk past A -- caller guarantees those bytes are in smem).
template <int K4, int LDA, int LDB>
static __device__ __forceinline__ void mm_tile_v(const float* __restrict__ A,
                                                 const float* __restrict__ B,
                                                 int row0, int col0,
                                                 u64 c[8][4]) {
    const float* Ab = A + row0 * LDA;
    const u64*   Bb = (const u64*)(B + col0);

    float4 a[8];
#pragma unroll
    for (int i = 0; i < 8; i++)
        a[i] = *(const float4*)(Ab + i * LDA);
    u64 b0 = Bb[0], b1 = Bb[1], b2 = Bb[2], b3 = Bb[3];

#pragma unroll 2
    for (int kk = 0; kk < K4; kk++) {
#pragma unroll
        for (int j = 0; j < 4; j++) {
            const int k = 4 * kk + j;
            // prefetch next k's B fragment (over-reads one row at the very end)
            const u64* Br = Bb + (size_t)(k + 1) * (LDB / 2);
            u64 n0 = Br[0], n1 = Br[1], n2 = Br[2], n3 = Br[3];
            float4 an[8];
            if (j == 3) {   // prefetch next 4-k A chunk (over-reads once at end)
#pragma unroll
                for (int i = 0; i < 8; i++)
                    an[i] = *(const float4*)(Ab + i * LDA + 4 * (kk + 1));
            }
#pragma unroll
            for (int i = 0; i < 8; i++) {
                const float* af = (const float*)&a[i];
                float av = af[j];
                u64 a2 = pack2(av, av);
                c[i][0] = fma2(a2, b0, c[i][0]);
                c[i][1] = fma2(a2, b1, c[i][1]);
                c[i][2] = fma2(a2, b2, c[i][2]);
                c[i][3] = fma2(a2, b3, c[i][3]);
            }
            b0 = n0; b1 = n1; b2 = n2; b3 = n3;
            if (j == 3) {
#pragma unroll
                for (int i = 0; i < 8; i++) a[i] = an[i];
            }
        }
    }
}

static __device__ __forceinline__ void store_relu_bias(float* __restrict__ dst,
                                                       int row0, int col0,
                                                       const u64 c[8][4],
                                                       const float* __restrict__ bias) {
#pragma unroll
    for (int i = 0; i < 8; i++) {
        float4* drow = (float4*)(dst + (row0 + i) * LDH + col0);
#pragma unroll
        for (int q = 0; q < 2; q++) {
            float2 v0 = unpack2(c[i][2 * q + 0]);
            float2 v1 = unpack2(c[i][2 * q + 1]);
            float4 o;
            o.x = fmaxf(v0.x + bias[col0 + 4 * q + 0], 0.0f);
            o.y = fmaxf(v0.y + bias[col0 + 4 * q + 1], 0.0f);
            o.z = fmaxf(v1.x + bias[col0 + 4 * q + 2], 0.0f);
            o.w = fmaxf(v1.y + bias[col0 + 4 * q + 3], 0.0f);
            drow[q] = o;
        }
    }
}

__global__ void __launch_bounds__(NTHREADS, 1)
sde_rollout_kernel(const float* __restrict__ X0, const float* __restrict__ V0,
                   const float* __restrict__ obs, const float* __restrict__ noise,
                   const float* __restrict__ W1, const float* __restrict__ b1,
                   const float* __restrict__ W2, const float* __restrict__ b2,
                   const float* __restrict__ W3, const float* __restrict__ b3,
                   float* __restrict__ out) {
    extern __shared__ float sm[];
    float* W1s = sm;                        // 28*128 = 3584 (rows 25..27 zero)
    float* b1s = W1s + KIN * HDIM;          // 128
    float* W2s = b1s + HDIM;                // 128*128 = 16384
    float* b2s = W2s + HDIM * HDIM;         // 128
    float* W3s = b2s + HDIM;                // 128*16 = 2048
    float* b3s = W3s + HDIM * DDIM;         // 16
    float* sIn = b3s + 16;                  // 128*28 = 3584
    float* sH  = sIn + BLK_P * LDIN;        // 128*132 = 16896
    float* sV  = sH + BLK_P * LDH;          // 128
    // total = 42896 floats = 171.6 KB

    const int tid = threadIdx.x;
    const int pbase = blockIdx.x * BLK_P;

    // ---- cooperative weight load ----
    for (int i = tid; i < (25 * HDIM) / 4; i += NTHREADS)
        ((float4*)W1s)[i] = ((const float4*)W1)[i];
    for (int i = tid; i < 3 * HDIM; i += NTHREADS)
        W1s[25 * HDIM + i] = 0.0f;                       // zero pad rows 25..27
    for (int i = tid; i < (HDIM * HDIM) / 4; i += NTHREADS)
        ((float4*)W2s)[i] = ((const float4*)W2)[i];
    for (int i = tid; i < (HDIM * DDIM) / 4; i += NTHREADS)
        ((float4*)W3s)[i] = ((const float4*)W3)[i];
    if (tid < HDIM) { b1s[tid] = b1[tid]; b2s[tid] = b2[tid]; }
    if (tid < DDIM) b3s[tid] = b3[tid];

    // ---- init particle state: sIn row = [t, X(16), obs(8), 0,0,0] ----
    const int p  = tid >> 1;
    const int dh = (tid & 1) * 8;
    const int pg = pbase + p;
    {
        float4 xa = *(const float4*)(X0 + (size_t)pg * DDIM + dh);
        float4 xb = *(const float4*)(X0 + (size_t)pg * DDIM + dh + 4);
        float* row = sIn + p * LDIN;
        row[1 + dh + 0] = xa.x; row[1 + dh + 1] = xa.y;
        row[1 + dh + 2] = xa.z; row[1 + dh + 3] = xa.w;
        row[1 + dh + 4] = xb.x; row[1 + dh + 5] = xb.y;
        row[1 + dh + 6] = xb.z; row[1 + dh + 7] = xb.w;
        if ((tid & 1) == 0) {
            row[0] = 0.0f;                 // t = times[0] = 0
            sV[p] = V0[pg];
#pragma unroll
            for (int j = 0; j < PDIM; j++)
                row[1 + DDIM + j] = obs[(size_t)pg * PDIM + j];
            row[25] = 0.0f; row[26] = 0.0f; row[27] = 0.0f;   // k-pad
        }
    }
    __syncthreads();

    const float dt   = (float)(1.0 / (double)M_STEPS);  // T = 1
    const float sqdt = sqrtf(dt);
    const int ty = tid >> 4, tx = tid & 15;
    const int row0 = ty * 8, col0 = tx * 8;

    for (int m = 0; m < M_STEPS; m++) {
        // ---- layer 1: h1 = relu(In @ W1 + b1), K padded to 28 ----
        u64 c[8][4];
#pragma unroll
        for (int i = 0; i < 8; i++) { c[i][0]=0; c[i][1]=0; c[i][2]=0; c[i][3]=0; }
        mm_tile_v<KIN / 4, LDIN, HDIM>(sIn, W1s, row0, col0, c);
        store_relu_bias(sH, row0, col0, c, b1s);
        __syncthreads();

        // ---- layer 2: h2 = relu(h1 @ W2 + b2) ----
#pragma unroll
        for (int i = 0; i < 8; i++) { c[i][0]=0; c[i][1]=0; c[i][2]=0; c[i][3]=0; }
        mm_tile_v<HDIM / 4, LDH, HDIM>(sH, W2s, row0, col0, c);

        // prefetch this step's noise now: DRAM latency hides behind the
        // store + 2 syncs + layer-3 mainloop below
        const float* np = noise + (((size_t)m * N_PART + pg) * DDIM + dh);
        float4 e0 = *(const float4*)np;
        float4 e1 = *(const float4*)(np + 4);

        __syncthreads();                            // everyone done reading h1
        store_relu_bias(sH, row0, col0, c, b2s);
        __syncthreads();

        // ---- layer 3: Z = h2 @ W3 + b3 (2 threads per particle, 8 dims each) ----
        u64 cz[4] = {0, 0, 0, 0};
        const float* hrow = sH + p * LDH;
#pragma unroll 4
        for (int kk = 0; kk < HDIM / 4; kk++) {
            float4 hv = *(const float4*)(hrow + 4 * kk);
            const float* hf = (const float*)&hv;
#pragma unroll
            for (int j = 0; j < 4; j++) {
                const int k = 4 * kk + j;
                u64 a2 = pack2(hf[j], hf[j]);
                ulonglong2 w01 = *(const ulonglong2*)(W3s + k * DDIM + dh);
                ulonglong2 w23 = *(const ulonglong2*)(W3s + k * DDIM + dh + 4);
                cz[0] = fma2(a2, w01.x, cz[0]);
                cz[1] = fma2(a2, w01.y, cz[1]);
                cz[2] = fma2(a2, w23.x, cz[2]);
                cz[3] = fma2(a2, w23.y, cz[3]);
            }
        }
        float z[8];
#pragma unroll
        for (int j4 = 0; j4 < 4; j4++) {
            float2 v = unpack2(cz[j4]);
            z[2 * j4 + 0] = v.x + b3s[dh + 2 * j4 + 0];
            z[2 * j4 + 1] = v.y + b3s[dh + 2 * j4 + 1];
        }
        float eps[8] = {e0.x, e0.y, e0.z, e0.w, e1.x, e1.y, e1.z, e1.w};

        float zz = 0.0f, zw = 0.0f;
#pragma unroll
        for (int j = 0; j < 8; j++) {
            zz = fmaf(z[j], z[j], zz);
            zw = fmaf(z[j], sqdt * eps[j], zw);
        }
        zz += __shfl_xor_sync(0xffffffffu, zz, 1);
        zw += __shfl_xor_sync(0xffffffffu, zw, 1);

        // X <- X*(1-dt) + sqrt(dt)*eps   (sigma = 1)
        float* xr = sIn + p * LDIN + 1 + dh;
#pragma unroll
        for (int j = 0; j < 8; j++)
            xr[j] = fmaf(xr[j], 1.0f - dt, sqdt * eps[j]);

        if ((tid & 1) == 0) {
            sV[p] = sV[p] + dt * 0.5f * zz + zw;     // V update
            sIn[p * LDIN] = (float)(m + 1) * dt;     // t for next step
        }
        __syncthreads();
    }

    // ---- write outputs: X (N*16) then V (N) ----
    {
        float* xo = out + (size_t)pg * DDIM + dh;
        const float* xr = sIn + p * LDIN + 1 + dh;
        float4 o0, o1;
        o0.x = xr[0]; o0.y = xr[1]; o0.z = xr[2]; o0.w = xr[3];
        o1.x = xr[4]; o1.y = xr[5]; o1.z = xr[6]; o1.w = xr[7];
        *(float4*)xo = o0;
        *(float4*)(xo + 4) = o1;
        if ((tid & 1) == 0) out[(size_t)N_PART * DDIM + pg] = sV[p];
    }
}

extern "C" void kernel_launch(void* const* d_in, const int* in_sizes, int n_in,
                              void* d_out, int out_size) {
    const float* X0    = (const float*)d_in[0];
    const float* V0    = (const float*)d_in[1];
    const float* obs   = (const float*)d_in[2];
    const float* noise = (const float*)d_in[3];
    const float* W1    = (const float*)d_in[4];
    const float* b1    = (const float*)d_in[5];
    const float* W2    = (const float*)d_in[6];
    const float* b2    = (const float*)d_in[7];
    const float* W3    = (const float*)d_in[8];
    const float* b3    = (const float*)d_in[9];
    float* out = (float*)d_out;

    const size_t smem_bytes =
        (size_t)(KIN * HDIM + HDIM + HDIM * HDIM + HDIM + HDIM * DDIM + 16 +
                 BLK_P * LDIN + BLK_P * LDH + BLK_P) * sizeof(float);

    cudaFuncSetAttribute(sde_rollout_kernel,
                         cudaFuncAttributeMaxDynamicSharedMemorySize,
                         (int)smem_bytes);

    sde_rollout_kernel<<<N_PART / BLK_P, NTHREADS, smem_bytes>>>(
        X0, V0, obs, noise, W1, b1, W2, b2, W3, b3, out);
}

// round 9
// speedup vs baseline: 1.1310x; 1.0661x over previous
#include <cuda_runtime.h>
#include <math.h>

#define N_PART   16384
#define DDIM     16
#define PDIM     8
#define M_STEPS  50
#define HDIM     128
#define KIN      28        // padded 1 + D + P (25) -> 28 for float4 k-vectorization
#define BLK_P    128       // particles per CTA
#define NTHREADS 256
#define LDIN     28        // sIn row stride (mult of 4, 16B-aligned rows)
#define LDH      132       // sH row stride (mult of 4)

typedef unsigned long long u64;

static __device__ __forceinline__ u64 pack2(float x, float y) {
    u64 r;
    asm("mov.b64 %0, {%1, %2};" : "=l"(r) : "f"(x), "f"(y));
    return r;
}
static __device__ __forceinline__ u64 fma2(u64 a, u64 b, u64 c) {
    u64 d;
    asm("fma.rn.f32x2 %0, %1, %2, %3;" : "=l"(d) : "l"(a), "l"(b), "l"(c));
    return d;
}
static __device__ __forceinline__ float2 unpack2(u64 v) {
    float2 f;
    asm("mov.b64 {%0, %1}, %2;" : "=f"(f.x), "=f"(f.y) : "l"(v));
    return f;
}

// C tile: 8 rows (ty + 16*i) x 8 cols ({4tx..4tx+3} U {64+4tx..64+4tx+3}).
//   c[i][0..1] <-> cols 4tx..4tx+3 ; c[i][2..3] <-> cols 64+4tx..64+4tx+3.
// A: rows at stride 16*LDA, k-chunks of 4 read as float4 (conflict-free:
//    the 2 ty rows per warp are 132 words apart, 132 mod 32 = 4).
// B: per k, two float4 at [k*LDB + 4tx] and [k*LDB + 64 + 4tx] -- lanes
//    contiguous 16B -> conflict-free LDS.128. Prefetched one k ahead.
// Over-reads one B row / one A chunk past the end (caller guarantees smem).
template <int K4, int LDA, int LDB>
static __device__ __forceinline__ void mm_tile_v(const float* __restrict__ A,
                                                 const float* __restrict__ B,
                                                 u64 c[8][4]) {
    float4 a[8];
#pragma unroll
    for (int i = 0; i < 8; i++)
        a[i] = *(const float4*)(A + i * 16 * LDA);
    float4 bA = *(const float4*)(B);
    float4 bB = *(const float4*)(B + 64);

#pragma unroll 2
    for (int kk = 0; kk < K4; kk++) {
#pragma unroll
        for (int j = 0; j < 4; j++) {
            const int k = 4 * kk + j;
            // prefetch next k's B fragments (over-reads one row at the end)
            float4 nA = *(const float4*)(B + (size_t)(k + 1) * LDB);
            float4 nB = *(const float4*)(B + (size_t)(k + 1) * LDB + 64);
            float4 an[8];
            if (j == 3) {   // prefetch next 4-k A chunk (over-reads once at end)
#pragma unroll
                for (int i = 0; i < 8; i++)
                    an[i] = *(const float4*)(A + i * 16 * LDA + 4 * (kk + 1));
            }
            const u64* bAp = (const u64*)&bA;
            const u64* bBp = (const u64*)&bB;
            u64 b0 = bAp[0], b1 = bAp[1], b2 = bBp[0], b3 = bBp[1];
#pragma unroll
            for (int i = 0; i < 8; i++) {
                const float* af = (const float*)&a[i];
                float av = af[j];
                u64 a2 = pack2(av, av);
                c[i][0] = fma2(a2, b0, c[i][0]);
                c[i][1] = fma2(a2, b1, c[i][1]);
                c[i][2] = fma2(a2, b2, c[i][2]);
                c[i][3] = fma2(a2, b3, c[i][3]);
            }
            bA = nA; bB = nB;
            if (j == 3) {
#pragma unroll
                for (int i = 0; i < 8; i++) a[i] = an[i];
            }
        }
    }
}

// store with bias+relu: rows ty+16i, cols 4tx (c[i][0..1]) and 64+4tx (c[i][2..3])
static __device__ __forceinline__ void store_relu_bias(float* __restrict__ dst,
                                                       int ty, int tx,
                                                       const u64 c[8][4],
                                                       float4 biasA, float4 biasB) {
#pragma unroll
    for (int i = 0; i < 8; i++) {
        float* drow = dst + (ty + 16 * i) * LDH;
        float2 v0 = unpack2(c[i][0]);
        float2 v1 = unpack2(c[i][1]);
        float4 o;
        o.x = fmaxf(v0.x + biasA.x, 0.0f);
        o.y = fmaxf(v0.y + biasA.y, 0.0f);
        o.z = fmaxf(v1.x + biasA.z, 0.0f);
        o.w = fmaxf(v1.y + biasA.w, 0.0f);
        *(float4*)(drow + 4 * tx) = o;
        float2 w0 = unpack2(c[i][2]);
        float2 w1 = unpack2(c[i][3]);
        float4 p;
        p.x = fmaxf(w0.x + biasB.x, 0.0f);
        p.y = fmaxf(w0.y + biasB.y, 0.0f);
        p.z = fmaxf(w1.x + biasB.z, 0.0f);
        p.w = fmaxf(w1.y + biasB.w, 0.0f);
        *(float4*)(drow + 64 + 4 * tx) = p;
    }
}

__global__ void __launch_bounds__(NTHREADS, 1)
sde_rollout_kernel(const float* __restrict__ X0, const float* __restrict__ V0,
                   const float* __restrict__ obs, const float* __restrict__ noise,
                   const float* __restrict__ W1, const float* __restrict__ b1,
                   const float* __restrict__ W2, const float* __restrict__ b2,
                   const float* __restrict__ W3, const float* __restrict__ b3,
                   float* __restrict__ out) {
    extern __shared__ float sm[];
    float* W1s = sm;                        // 28*128 = 3584 (rows 25..27 zero)
    float* b1s = W1s + KIN * HDIM;          // 128
    float* W2s = b1s + HDIM;                // 128*128 = 16384
    float* b2s = W2s + HDIM * HDIM;         // 128
    float* W3s = b2s + HDIM;                // 128*16 = 2048
    float* b3s = W3s + HDIM * DDIM;         // 16
    float* sIn = b3s + 16;                  // 128*28 = 3584
    float* sH  = sIn + BLK_P * LDIN;        // 128*132 = 16896
    float* sV  = sH + BLK_P * LDH;          // 128

    const int tid = threadIdx.x;
    const int pbase = blockIdx.x * BLK_P;

    // ---- cooperative weight load ----
    for (int i = tid; i < (25 * HDIM) / 4; i += NTHREADS)
        ((float4*)W1s)[i] = ((const float4*)W1)[i];
    for (int i = tid; i < 3 * HDIM; i += NTHREADS)
        W1s[25 * HDIM + i] = 0.0f;                       // zero pad rows 25..27
    for (int i = tid; i < (HDIM * HDIM) / 4; i += NTHREADS)
        ((float4*)W2s)[i] = ((const float4*)W2)[i];
    for (int i = tid; i < (HDIM * DDIM) / 4; i += NTHREADS)
        ((float4*)W3s)[i] = ((const float4*)W3)[i];
    if (tid < HDIM) { b1s[tid] = b1[tid]; b2s[tid] = b2[tid]; }
    if (tid < DDIM) b3s[tid] = b3[tid];

    // ---- init particle state: sIn row = [t, X(16), obs(8), 0,0,0] ----
    const int p  = tid >> 1;
    const int dh = (tid & 1) * 8;
    const int pg = pbase + p;
    {
        float4 xa = *(const float4*)(X0 + (size_t)pg * DDIM + dh);
        float4 xb = *(const float4*)(X0 + (size_t)pg * DDIM + dh + 4);
        float* row = sIn + p * LDIN;
        row[1 + dh + 0] = xa.x; row[1 + dh + 1] = xa.y;
        row[1 + dh + 2] = xa.z; row[1 + dh + 3] = xa.w;
        row[1 + dh + 4] = xb.x; row[1 + dh + 5] = xb.y;
        row[1 + dh + 6] = xb.z; row[1 + dh + 7] = xb.w;
        if ((tid & 1) == 0) {
            row[0] = 0.0f;                 // t = times[0] = 0
            sV[p] = V0[pg];
#pragma unroll
            for (int j = 0; j < PDIM; j++)
                row[1 + DDIM + j] = obs[(size_t)pg * PDIM + j];
            row[25] = 0.0f; row[26] = 0.0f; row[27] = 0.0f;   // k-pad
        }
    }
    __syncthreads();

    const float dt   = (float)(1.0 / (double)M_STEPS);  // T = 1
    const float sqdt = sqrtf(dt);
    const int ty = tid >> 4, tx = tid & 15;

    // loop-invariant bias fragments -> registers
    const float4 b1A = *(const float4*)(b1s + 4 * tx);
    const float4 b1B = *(const float4*)(b1s + 64 + 4 * tx);
    const float4 b2A = *(const float4*)(b2s + 4 * tx);
    const float4 b2B = *(const float4*)(b2s + 64 + 4 * tx);
    const float4 b3a = *(const float4*)(b3s + dh);
    const float4 b3b = *(const float4*)(b3s + dh + 4);

    for (int m = 0; m < M_STEPS; m++) {
        // ---- layer 1: h1 = relu(In @ W1 + b1), K padded to 28 ----
        u64 c[8][4];
#pragma unroll
        for (int i = 0; i < 8; i++) { c[i][0]=0; c[i][1]=0; c[i][2]=0; c[i][3]=0; }
        mm_tile_v<KIN / 4, LDIN, HDIM>(sIn + ty * LDIN, W1s + 4 * tx, c);
        store_relu_bias(sH, ty, tx, c, b1A, b1B);
        __syncthreads();

        // ---- layer 2: h2 = relu(h1 @ W2 + b2) ----
#pragma unroll
        for (int i = 0; i < 8; i++) { c[i][0]=0; c[i][1]=0; c[i][2]=0; c[i][3]=0; }
        mm_tile_v<HDIM / 4, LDH, HDIM>(sH + ty * LDH, W2s + 4 * tx, c);

        // prefetch this step's noise: DRAM latency hides behind the
        // store + 2 syncs + layer-3 mainloop below
        const float* np = noise + (((size_t)m * N_PART + pg) * DDIM + dh);
        float4 e0 = *(const float4*)np;
        float4 e1 = *(const float4*)(np + 4);

        __syncthreads();                            // everyone done reading h1
        store_relu_bias(sH, ty, tx, c, b2A, b2B);
        __syncthreads();

        // ---- layer 3: Z = h2 @ W3 + b3 (2 threads per particle, 8 dims each) ----
        u64 cz[4] = {0, 0, 0, 0};
        const float* hrow = sH + p * LDH;
#pragma unroll 4
        for (int kk = 0; kk < HDIM / 4; kk++) {
            float4 hv = *(const float4*)(hrow + 4 * kk);
            const float* hf = (const float*)&hv;
#pragma unroll
            for (int j = 0; j < 4; j++) {
                const int k = 4 * kk + j;
                u64 a2 = pack2(hf[j], hf[j]);
                ulonglong2 w01 = *(const ulonglong2*)(W3s + k * DDIM + dh);
                ulonglong2 w23 = *(const ulonglong2*)(W3s + k * DDIM + dh + 4);
                cz[0] = fma2(a2, w01.x, cz[0]);
                cz[1] = fma2(a2, w01.y, cz[1]);
                cz[2] = fma2(a2, w23.x, cz[2]);
                cz[3] = fma2(a2, w23.y, cz[3]);
            }
        }
        const float* b3f = (const float*)&b3a;
        const float* b3g = (const float*)&b3b;
        float z[8];
        {
            float2 v0 = unpack2(cz[0]), v1 = unpack2(cz[1]);
            float2 v2 = unpack2(cz[2]), v3 = unpack2(cz[3]);
            z[0] = v0.x + b3f[0]; z[1] = v0.y + b3f[1];
            z[2] = v1.x + b3f[2]; z[3] = v1.y + b3f[3];
            z[4] = v2.x + b3g[0]; z[5] = v2.y + b3g[1];
            z[6] = v3.x + b3g[2]; z[7] = v3.y + b3g[3];
        }
        float eps[8] = {e0.x, e0.y, e0.z, e0.w, e1.x, e1.y, e1.z, e1.w};

        float zz = 0.0f, zw = 0.0f;
#pragma unroll
        for (int j = 0; j < 8; j++) {
            zz = fmaf(z[j], z[j], zz);
            zw = fmaf(z[j], sqdt * eps[j], zw);
        }
        zz += __shfl_xor_sync(0xffffffffu, zz, 1);
        zw += __shfl_xor_sync(0xffffffffu, zw, 1);

        // X <- X*(1-dt) + sqrt(dt)*eps   (sigma = 1)
        float* xr = sIn + p * LDIN + 1 + dh;
#pragma unroll
        for (int j = 0; j < 8; j++)
            xr[j] = fmaf(xr[j], 1.0f - dt, sqdt * eps[j]);

        if ((tid & 1) == 0) {
            sV[p] = sV[p] + dt * 0.5f * zz + zw;     // V update
            sIn[p * LDIN] = (float)(m + 1) * dt;     // t for next step
        }
        __syncthreads();
    }

    // ---- write outputs: X (N*16) then V (N) ----
    {
        float* xo = out + (size_t)pg * DDIM + dh;
        const float* xr = sIn + p * LDIN + 1 + dh;
        float4 o0, o1;
        o0.x = xr[0]; o0.y = xr[1]; o0.z = xr[2]; o0.w = xr[3];
        o1.x = xr[4]; o1.y = xr[5]; o1.z = xr[6]; o1.w = xr[7];
        *(float4*)xo = o0;
        *(float4*)(xo + 4) = o1;
        if ((tid & 1) == 0) out[(size_t)N_PART * DDIM + pg] = sV[p];
    }
}

extern "C" void kernel_launch(void* const* d_in, const int* in_sizes, int n_in,
                              void* d_out, int out_size) {
    const float* X0    = (const float*)d_in[0];
    const float* V0    = (const float*)d_in[1];
    const float* obs   = (const float*)d_in[2];
    const float* noise = (const float*)d_in[3];
    const float* W1    = (const float*)d_in[4];
    const float* b1    = (const float*)d_in[5];
    const float* W2    = (const float*)d_in[6];
    const float* b2    = (const float*)d_in[7];
    const float* W3    = (const float*)d_in[8];
    const float* b3    = (const float*)d_in[9];
    float* out = (float*)d_out;

    const size_t smem_bytes =
        (size_t)(KIN * HDIM + HDIM + HDIM * HDIM + HDIM + HDIM * DDIM + 16 +
                 BLK_P * LDIN + BLK_P * LDH + BLK_P) * sizeof(float);

    cudaFuncSetAttribute(sde_rollout_kernel,
                         cudaFuncAttributeMaxDynamicSharedMemorySize,
                         (int)smem_bytes);

    sde_rollout_kernel<<<N_PART / BLK_P, NTHREADS, smem_bytes>>>(
        X0, V0, obs, noise, W1, b1, W2, b2, W3, b3, out);
}

// round 10
// speedup vs baseline: 1.1842x; 1.0471x over previous
#include <cuda_runtime.h>
#include <math.h>

#define N_PART   16384
#define DDIM     16
#define PDIM     8
#define M_STEPS  50
#define HDIM     128
#define BLK_P    128       // particles per CTA
#define NTHREADS 256
#define LDIN     16        // sIn row stride: X only (16 floats)
#define LDH      132       // sH / base row stride (132 mod 32 = 4 -> conflict-free)

typedef unsigned long long u64;

static __device__ __forceinline__ u64 pack2(float x, float y) {
    u64 r;
    asm("mov.b64 %0, {%1, %2};" : "=l"(r) : "f"(x), "f"(y));
    return r;
}
static __device__ __forceinline__ u64 fma2(u64 a, u64 b, u64 c) {
    u64 d;
    asm("fma.rn.f32x2 %0, %1, %2, %3;" : "=l"(d) : "l"(a), "l"(b), "l"(c));
    return d;
}
static __device__ __forceinline__ float2 unpack2(u64 v) {
    float2 f;
    asm("mov.b64 {%0, %1}, %2;" : "=f"(f.x), "=f"(f.y) : "l"(v));
    return f;
}

// C tile: 8 rows (ty + 16*i) x 8 cols ({4tx..4tx+3} U {64+4tx..64+4tx+3}).
// A: rows at stride 16*LDA, k-chunks of 4 read as float4.
// B: per k, two float4 at [k*LDB + 4tx] and [k*LDB + 64 + 4tx]; prefetch 1 k ahead.
// Over-reads one B row / one A chunk past the end (must stay inside smem).
// Accumulates into caller-initialized c.
template <int K4, int LDA, int LDB>
static __device__ __forceinline__ void mm_tile_v(const float* __restrict__ A,
                                                 const float* __restrict__ B,
                                                 u64 c[8][4]) {
    float4 a[8];
#pragma unroll
    for (int i = 0; i < 8; i++)
        a[i] = *(const float4*)(A + i * 16 * LDA);
    float4 bA = *(const float4*)(B);
    float4 bB = *(const float4*)(B + 64);

#pragma unroll 2
    for (int kk = 0; kk < K4; kk++) {
#pragma unroll
        for (int j = 0; j < 4; j++) {
            const int k = 4 * kk + j;
            float4 nA = *(const float4*)(B + (size_t)(k + 1) * LDB);
            float4 nB = *(const float4*)(B + (size_t)(k + 1) * LDB + 64);
            float4 an[8];
            if (j == 3) {
#pragma unroll
                for (int i = 0; i < 8; i++)
                    an[i] = *(const float4*)(A + i * 16 * LDA + 4 * (kk + 1));
            }
            const u64* bAp = (const u64*)&bA;
            const u64* bBp = (const u64*)&bB;
            u64 b0 = bAp[0], b1 = bAp[1], b2 = bBp[0], b3 = bBp[1];
#pragma unroll
            for (int i = 0; i < 8; i++) {
                const float* af = (const float*)&a[i];
                float av = af[j];
                u64 a2 = pack2(av, av);
                c[i][0] = fma2(a2, b0, c[i][0]);
                c[i][1] = fma2(a2, b1, c[i][1]);
                c[i][2] = fma2(a2, b2, c[i][2]);
                c[i][3] = fma2(a2, b3, c[i][3]);
            }
            bA = nA; bB = nB;
            if (j == 3) {
#pragma unroll
                for (int i = 0; i < 8; i++) a[i] = an[i];
            }
        }
    }
}

// relu(c + bias) -> dst  (rows ty+16i, col groups 4tx and 64+4tx)
static __device__ __forceinline__ void store_relu_bias(float* __restrict__ dst,
                                                       int ty, int tx,
                                                       const u64 c[8][4],
                                                       float4 biasA, float4 biasB) {
#pragma unroll
    for (int i = 0; i < 8; i++) {
        float* drow = dst + (ty + 16 * i) * LDH;
        float2 v0 = unpack2(c[i][0]);
        float2 v1 = unpack2(c[i][1]);
        float4 o;
        o.x = fmaxf(v0.x + biasA.x, 0.0f);
        o.y = fmaxf(v0.y + biasA.y, 0.0f);
        o.z = fmaxf(v1.x + biasA.z, 0.0f);
        o.w = fmaxf(v1.y + biasA.w, 0.0f);
        *(float4*)(drow + 4 * tx) = o;
        float2 w0 = unpack2(c[i][2]);
        float2 w1 = unpack2(c[i][3]);
        float4 p;
        p.x = fmaxf(w0.x + biasB.x, 0.0f);
        p.y = fmaxf(w0.y + biasB.y, 0.0f);
        p.z = fmaxf(w1.x + biasB.z, 0.0f);
        p.w = fmaxf(w1.y + biasB.w, 0.0f);
        *(float4*)(drow + 64 + 4 * tx) = p;
    }
}

// relu(c) -> dst  (bias already folded into the accumulator via base)
static __device__ __forceinline__ void store_relu(float* __restrict__ dst,
                                                  int ty, int tx,
                                                  const u64 c[8][4]) {
#pragma unroll
    for (int i = 0; i < 8; i++) {
        float* drow = dst + (ty + 16 * i) * LDH;
        float2 v0 = unpack2(c[i][0]);
        float2 v1 = unpack2(c[i][1]);
        float4 o;
        o.x = fmaxf(v0.x, 0.0f); o.y = fmaxf(v0.y, 0.0f);
        o.z = fmaxf(v1.x, 0.0f); o.w = fmaxf(v1.y, 0.0f);
        *(float4*)(drow + 4 * tx) = o;
        float2 w0 = unpack2(c[i][2]);
        float2 w1 = unpack2(c[i][3]);
        float4 p;
        p.x = fmaxf(w0.x, 0.0f); p.y = fmaxf(w0.y, 0.0f);
        p.z = fmaxf(w1.x, 0.0f); p.w = fmaxf(w1.y, 0.0f);
        *(float4*)(drow + 64 + 4 * tx) = p;
    }
}

__global__ void __launch_bounds__(NTHREADS, 1)
sde_rollout_kernel(const float* __restrict__ X0, const float* __restrict__ V0,
                   const float* __restrict__ obs, const float* __restrict__ noise,
                   const float* __restrict__ W1, const float* __restrict__ b1,
                   const float* __restrict__ W2, const float* __restrict__ b2,
                   const float* __restrict__ W3, const float* __restrict__ b3,
                   float* __restrict__ out) {
    extern __shared__ float sm[];
    float* W1xs = sm;                       // 16*128 = 2048   (W1 rows 1..16: X part)
    float* w1ts = W1xs + 16 * HDIM;         // 128             (W1 row 0: t part)
    float* b1s  = w1ts + HDIM;              // 128
    float* W2s  = b1s + HDIM;               // 128*128 = 16384
    float* b2s  = W2s + HDIM * HDIM;        // 128
    float* W3s  = b2s + HDIM;               // 128*16 = 2048
    float* b3s  = W3s + HDIM * DDIM;        // 16
    float* sIn  = b3s + 16;                 // 128*16 = 2048   (X state only)
    float* sH   = sIn + BLK_P * LDIN;       // 128*132 = 16896
    float* sV   = sH + BLK_P * LDH;         // 128
    float* base = sV + BLK_P;               // 128*132 = 16896 (obs@W1o + b1, per particle)
    // total = 56848 floats = 227392 B

    const int tid = threadIdx.x;
    const int pbase = blockIdx.x * BLK_P;

    // ---- cooperative weight load ----
    // W1 rows: [0]=t, [1..16]=X, [17..24]=obs
    for (int i = tid; i < (16 * HDIM) / 4; i += NTHREADS)
        ((float4*)W1xs)[i] = ((const float4*)(W1 + HDIM))[i];       // rows 1..16
    for (int i = tid; i < (HDIM * HDIM) / 4; i += NTHREADS)
        ((float4*)W2s)[i] = ((const float4*)W2)[i];
    for (int i = tid; i < (HDIM * DDIM) / 4; i += NTHREADS)
        ((float4*)W3s)[i] = ((const float4*)W3)[i];
    if (tid < HDIM) {
        w1ts[tid] = W1[tid];                                        // row 0
        b1s[tid] = b1[tid];
        b2s[tid] = b2[tid];
    }
    if (tid < DDIM) b3s[tid] = b3[tid];
    // W1 obs rows (17..24) -> scratch: base buffer rows 0..7 (stride LDH)
    for (int i = tid; i < PDIM * HDIM; i += NTHREADS) {
        int k = i / HDIM, cc = i % HDIM;
        base[k * LDH + cc] = W1[(17 + k) * HDIM + cc];
    }

    // ---- init particle state: sIn = X, sV = V; obs -> sH scratch rows ----
    const int p  = tid >> 1;
    const int dh = (tid & 1) * 8;
    const int pg = pbase + p;
    {
        float4 xa = *(const float4*)(X0 + (size_t)pg * DDIM + dh);
        float4 xb = *(const float4*)(X0 + (size_t)pg * DDIM + dh + 4);
        float* row = sIn + p * LDIN;
        *(float4*)(row + dh) = xa;
        *(float4*)(row + dh + 4) = xb;
        if ((tid & 1) == 0) {
            sV[p] = V0[pg];
#pragma unroll
            for (int j = 0; j < PDIM; j++)
                sH[p * LDH + j] = obs[(size_t)pg * PDIM + j];       // obs scratch
        }
    }
    __syncthreads();

    const int ty = tid >> 4, tx = tid & 15;

    // ---- precompute base = obs @ W1o + b1 (K=8 GEMM, once) ----
    {
        u64 c[8][4];
#pragma unroll
        for (int i = 0; i < 8; i++) { c[i][0]=0; c[i][1]=0; c[i][2]=0; c[i][3]=0; }
        mm_tile_v<2, LDH, LDH>(sH + ty * LDH, base + 4 * tx, c);    // A=obs rows, B=W1o rows
        __syncthreads();    // all reads of W1o scratch done before base is overwritten
        float4 b1A = *(const float4*)(b1s + 4 * tx);
        float4 b1B = *(const float4*)(b1s + 64 + 4 * tx);
#pragma unroll
        for (int i = 0; i < 8; i++) {
            float* drow = base + (ty + 16 * i) * LDH;
            float2 v0 = unpack2(c[i][0]), v1 = unpack2(c[i][1]);
            float4 o = { v0.x + b1A.x, v0.y + b1A.y, v1.x + b1A.z, v1.y + b1A.w };
            *(float4*)(drow + 4 * tx) = o;
            float2 w0 = unpack2(c[i][2]), w1 = unpack2(c[i][3]);
            float4 q = { w0.x + b1B.x, w0.y + b1B.y, w1.x + b1B.z, w1.y + b1B.w };
            *(float4*)(drow + 64 + 4 * tx) = q;
        }
    }
    __syncthreads();

    const float dt   = (float)(1.0 / (double)M_STEPS);  // T = 1
    const float sqdt = sqrtf(dt);

    // loop-invariant fragments -> registers
    const float4 b2A = *(const float4*)(b2s + 4 * tx);
    const float4 b2B = *(const float4*)(b2s + 64 + 4 * tx);
    const float4 b3a = *(const float4*)(b3s + dh);
    const float4 b3b = *(const float4*)(b3s + dh + 4);
    u64 w1tf[4];
    {
        float4 tA = *(const float4*)(w1ts + 4 * tx);
        float4 tB = *(const float4*)(w1ts + 64 + 4 * tx);
        const u64* ta = (const u64*)&tA; const u64* tb = (const u64*)&tB;
        w1tf[0] = ta[0]; w1tf[1] = ta[1]; w1tf[2] = tb[0]; w1tf[3] = tb[1];
    }

    for (int m = 0; m < M_STEPS; m++) {
        const float t = (float)m * dt;
        const u64 t2 = pack2(t, t);

        // ---- layer 1: h1 = relu(X@W1x + t*W1t + base), K=16 ----
        u64 c[8][4];
#pragma unroll
        for (int i = 0; i < 8; i++) {
            const float* brow = base + (ty + 16 * i) * LDH;
            float4 fA = *(const float4*)(brow + 4 * tx);
            float4 fB = *(const float4*)(brow + 64 + 4 * tx);
            const u64* fa = (const u64*)&fA; const u64* fb = (const u64*)&fB;
            c[i][0] = fma2(t2, w1tf[0], fa[0]);
            c[i][1] = fma2(t2, w1tf[1], fa[1]);
            c[i][2] = fma2(t2, w1tf[2], fb[0]);
            c[i][3] = fma2(t2, w1tf[3], fb[1]);
        }
        mm_tile_v<4, LDIN, HDIM>(sIn + ty * LDIN, W1xs + 4 * tx, c);
        store_relu(sH, ty, tx, c);
        __syncthreads();

        // ---- layer 2: h2 = relu(h1 @ W2 + b2) ----
#pragma unroll
        for (int i = 0; i < 8; i++) { c[i][0]=0; c[i][1]=0; c[i][2]=0; c[i][3]=0; }
        mm_tile_v<HDIM / 4, LDH, HDIM>(sH + ty * LDH, W2s + 4 * tx, c);

        // prefetch this step's noise (DRAM latency hides behind syncs + layer 3)
        const float* np = noise + (((size_t)m * N_PART + pg) * DDIM + dh);
        float4 e0 = *(const float4*)np;
        float4 e1 = *(const float4*)(np + 4);

        __syncthreads();                            // everyone done reading h1
        store_relu_bias(sH, ty, tx, c, b2A, b2B);
        __syncthreads();

        // ---- layer 3: Z = h2 @ W3 + b3 (2 threads/particle, 8 dims each) ----
        u64 cz[4] = {0, 0, 0, 0};
        const float* hrow = sH + p * LDH;
#pragma unroll 4
        for (int kk = 0; kk < HDIM / 4; kk++) {
            float4 hv = *(const float4*)(hrow + 4 * kk);
            const float* hf = (const float*)&hv;
#pragma unroll
            for (int j = 0; j < 4; j++) {
                const int k = 4 * kk + j;
                u64 a2 = pack2(hf[j], hf[j]);
                ulonglong2 w01 = *(const ulonglong2*)(W3s + k * DDIM + dh);
                ulonglong2 w23 = *(const ulonglong2*)(W3s + k * DDIM + dh + 4);
                cz[0] = fma2(a2, w01.x, cz[0]);
                cz[1] = fma2(a2, w01.y, cz[1]);
                cz[2] = fma2(a2, w23.x, cz[2]);
                cz[3] = fma2(a2, w23.y, cz[3]);
            }
        }
        const float* b3f = (const float*)&b3a;
        const float* b3g = (const float*)&b3b;
        float z[8];
        {
            float2 v0 = unpack2(cz[0]), v1 = unpack2(cz[1]);
            float2 v2 = unpack2(cz[2]), v3 = unpack2(cz[3]);
            z[0] = v0.x + b3f[0]; z[1] = v0.y + b3f[1];
            z[2] = v1.x + b3f[2]; z[3] = v1.y + b3f[3];
            z[4] = v2.x + b3g[0]; z[5] = v2.y + b3g[1];
            z[6] = v3.x + b3g[2]; z[7] = v3.y + b3g[3];
        }
        float eps[8] = {e0.x, e0.y, e0.z, e0.w, e1.x, e1.y, e1.z, e1.w};

        float zz = 0.0f, zw = 0.0f;
#pragma unroll
        for (int j = 0; j < 8; j++) {
            zz = fmaf(z[j], z[j], zz);
            zw = fmaf(z[j], sqdt * eps[j], zw);
        }
        zz += __shfl_xor_sync(0xffffffffu, zz, 1);
        zw += __shfl_xor_sync(0xffffffffu, zw, 1);

        // X <- X*(1-dt) + sqrt(dt)*eps   (sigma = 1)
        float* xr = sIn + p * LDIN + dh;
#pragma unroll
        for (int j = 0; j < 8; j++)
            xr[j] = fmaf(xr[j], 1.0f - dt, sqdt * eps[j]);

        if ((tid & 1) == 0)
            sV[p] = sV[p] + dt * 0.5f * zz + zw;     // V update
        __syncthreads();
    }

    // ---- write outputs: X (N*16) then V (N) ----
    {
        float* xo = out + (size_t)pg * DDIM + dh;
        const float* xr = sIn + p * LDIN + dh;
        *(float4*)xo = *(const float4*)xr;
        *(float4*)(xo + 4) = *(const float4*)(xr + 4);
        if ((tid & 1) == 0) out[(size_t)N_PART * DDIM + pg] = sV[p];
    }
}

extern "C" void kernel_launch(void* const* d_in, const int* in_sizes, int n_in,
                              void* d_out, int out_size) {
    const float* X0    = (const float*)d_in[0];
    const float* V0    = (const float*)d_in[1];
    const float* obs   = (const float*)d_in[2];
    const float* noise = (const float*)d_in[3];
    const float* W1    = (const float*)d_in[4];
    const float* b1    = (const float*)d_in[5];
    const float* W2    = (const float*)d_in[6];
    const float* b2    = (const float*)d_in[7];
    const float* W3    = (const float*)d_in[8];
    const float* b3    = (const float*)d_in[9];
    float* out = (float*)d_out;

    const size_t smem_bytes =
        (size_t)(16 * HDIM + HDIM + HDIM + HDIM * HDIM + HDIM + HDIM * DDIM + 16 +
                 BLK_P * LDIN + BLK_P * LDH + BLK_P + BLK_P * LDH) * sizeof(float);

    cudaFuncSetAttribute(sde_rollout_kernel,
                         cudaFuncAttributeMaxDynamicSharedMemorySize,
                         (int)smem_bytes);

    sde_rollout_kernel<<<N_PART / BLK_P, NTHREADS, smem_bytes>>>(
        X0, V0, obs, noise, W1, b1, W2, b2, W3, b3, out);
}